// round 5
// baseline (speedup 1.0000x reference)
#include <cuda_runtime.h>
#include <cuda_bf16.h>
#include <cstdint>

#define B_Q   256
#define N_MEM 50000
#define D_DIM 1024
#define NTILE 128
#define KC    64
#define NCHUNK (D_DIM / KC)                 // 16
#define NBLK  ((N_MEM + NTILE - 1) / NTILE) // 391

// SMEM layout (bytes, dynamic)
#define SM_MBAR  0        // full0,full1,empty0,empty1 (8B each)
#define SM_NORM  64       // 128 floats
#define SM_Q     1024     // 2 slots x 256 rows x 128B (bf16 SW128) = 64KB
#define SM_M     (SM_Q + 65536)   // 2 slots x 128 rows x 128B = 32KB
#define SMEM_TOTAL (SM_M + 32768)

__device__ unsigned long long g_best[B_Q];
__device__ int g_sel[B_Q];
__device__ __nv_bfloat16 g_qb[B_Q * D_DIM];

__device__ __forceinline__ uint32_t smem_u32(const void* p) {
    uint32_t a;
    asm("{ .reg .u64 t; cvta.to.shared.u64 t, %1; cvt.u32.u64 %0, t; }" : "=r"(a) : "l"(p));
    return a;
}
__device__ __forceinline__ unsigned int fkey(float f) {
    unsigned int u = __float_as_uint(f);
    return (u & 0x80000000u) ? ~u : (u | 0x80000000u);
}
#define SW128(off) ((off) ^ (((off) >> 3) & 0x70))

#define LDSM_X4(r0, r1, r2, r3, a) \
    asm volatile("ldmatrix.sync.aligned.m8n8.x4.shared.b16 {%0,%1,%2,%3}, [%4];" \
                 : "=r"(r0), "=r"(r1), "=r"(r2), "=r"(r3) : "r"(a))
#define LDSM_X4_T(r0, r1, r2, r3, a) \
    asm volatile("ldmatrix.sync.aligned.m8n8.x4.trans.shared.b16 {%0,%1,%2,%3}, [%4];" \
                 : "=r"(r0), "=r"(r1), "=r"(r2), "=r"(r3) : "r"(a))
#define MMA_BF16(d, a, b0, b1) \
    asm volatile("mma.sync.aligned.m16n8k16.row.col.f32.bf16.bf16.f32 " \
                 "{%0,%1,%2,%3}, {%4,%5,%6,%7}, {%8,%9}, {%0,%1,%2,%3};" \
                 : "+f"((d)[0]), "+f"((d)[1]), "+f"((d)[2]), "+f"((d)[3]) \
                 : "r"((a)[0]), "r"((a)[1]), "r"((a)[2]), "r"((a)[3]), "r"(b0), "r"(b1))

#define MBAR_INIT(mb, cnt) \
    asm volatile("mbarrier.init.shared.b64 [%0], %1;" :: "r"((uint32_t)(mb)), "r"((uint32_t)(cnt)) : "memory")
#define MBAR_ARRIVE(mb) \
    asm volatile("mbarrier.arrive.release.cta.shared::cta.b64 _, [%0];" :: "r"((uint32_t)(mb)) : "memory")
#define CP_ASYNC_16(dst, src) \
    asm volatile("cp.async.cg.shared.global [%0], [%1], 16;" :: "r"(dst), "l"(src) : "memory")
#define CP_ASYNC_COMMIT() asm volatile("cp.async.commit_group;" ::: "memory")
#define CP_ASYNC_WAIT_ALL() asm volatile("cp.async.wait_group 0;" ::: "memory")

__device__ __forceinline__ void mbar_wait(uint32_t mb, uint32_t parity) {
    uint32_t done;
    asm volatile(
        "{\n\t.reg .pred p;\n\t"
        "mbarrier.try_wait.parity.acquire.cta.shared::cta.b64 p, [%1], %2;\n\t"
        "selp.b32 %0, 1, 0, p;\n\t}"
        : "=r"(done) : "r"(mb), "r"(parity) : "memory");
    if (!done) {
        asm volatile(
            "{\n\t.reg .pred P1;\n\t"
            "WL_%=:\n\t"
            "mbarrier.try_wait.parity.acquire.cta.shared::cta.b64 P1, [%0], %1, 0x989680;\n\t"
            "@P1 bra.uni WD_%=;\n\t"
            "bra.uni WL_%=;\n\t"
            "WD_%=:\n\t}"
            :: "r"(mb), "r"(parity) : "memory");
    }
}

// Q fp32 -> bf16 once; reset g_best.
__global__ __launch_bounds__(256) void prep_kernel(const float* __restrict__ Q) {
    int idx = blockIdx.x * 256 + threadIdx.x;
    const float4 v = reinterpret_cast<const float4*>(Q)[idx];
    __nv_bfloat162 p0 = __float22bfloat162_rn(make_float2(v.x, v.y));
    __nv_bfloat162 p1 = __float22bfloat162_rn(make_float2(v.z, v.w));
    uint2 w;
    w.x = *reinterpret_cast<uint32_t*>(&p0);
    w.y = *reinterpret_cast<uint32_t*>(&p1);
    reinterpret_cast<uint2*>(g_qb)[idx] = w;
    if (blockIdx.x == 0) g_best[threadIdx.x] = 0ull;
}

// Warp-specialized: warps 0-7 consume (LDSM+MMA), warps 8-11 produce
// (Q via cp.async, M fp32->bf16 + norms). Double-buffered, mbarrier paced.
__global__ __launch_bounds__(384, 1) void simmax_mma(const float* __restrict__ Mptr) {
    extern __shared__ char smem[];
    const uint32_t sb = smem_u32(smem);
    const int tid = threadIdx.x;
    const int l   = tid & 31;
    const int wid = tid >> 5;
    const int ntile = blockIdx.x * NTILE;

    const uint32_t FULL0  = sb + SM_MBAR;
    const uint32_t FULL1  = sb + SM_MBAR + 8;
    const uint32_t EMPTY0 = sb + SM_MBAR + 16;
    const uint32_t EMPTY1 = sb + SM_MBAR + 24;

    float* norms = reinterpret_cast<float*>(smem + SM_NORM);
    if (tid == 0) {
        MBAR_INIT(FULL0, 128);  MBAR_INIT(FULL1, 128);   // 128 producer arrives
        MBAR_INIT(EMPTY0, 256); MBAR_INIT(EMPTY1, 256);  // 256 consumer arrives
    }
    if (tid < NTILE) norms[tid] = 0.0f;
    __syncthreads();

    if (wid >= 8) {
        // ================= PRODUCER (128 threads) =================
        const int p = tid - 256;
        int pe0 = 0, pe1 = 0;
        for (int c = 0; c < NCHUNK; c++) {
            const int slot = c & 1;
            if (c >= 2) {
                if (slot == 0) { mbar_wait(EMPTY0, pe0); pe0 ^= 1; }
                else           { mbar_wait(EMPTY1, pe1); pe1 ^= 1; }
            }
            const uint32_t qbase = sb + SM_Q + slot * 32768;

            // ---- Q chunk: 256 rows x 128B, 2048 16B segs, 16 per thread (cp.async)
#pragma unroll
            for (int i = 0; i < 16; i++) {
                int s = p + 128 * i;
                int qrow = s >> 3, qseg = s & 7;
                const void* src = g_qb + (size_t)qrow * D_DIM + c * KC + qseg * 8;
                uint32_t off = (uint32_t)(qrow * 128 + qseg * 16);
                CP_ASYNC_16(qbase + SW128(off), src);
            }
            CP_ASYNC_COMMIT();

            // ---- M chunk: 128 rows x 64 fp32 -> bf16, fused row sumsq
            //      (overlaps the in-flight Q cp.asyncs)
#pragma unroll
            for (int i = 0; i < 16; i++) {
                int s = p + 128 * i;
                int mrow = s >> 4, mseg = s & 15;   // 4 floats per seg
                int gn = ntile + mrow;
                float4 v = make_float4(0.f, 0.f, 0.f, 0.f);
                if (gn < N_MEM)
                    v = *reinterpret_cast<const float4*>(
                        Mptr + (size_t)gn * D_DIM + c * KC + mseg * 4);
                float sq = v.x * v.x + v.y * v.y + v.z * v.z + v.w * v.w;
                sq += __shfl_xor_sync(0xFFFFFFFFu, sq, 1);
                sq += __shfl_xor_sync(0xFFFFFFFFu, sq, 2);
                sq += __shfl_xor_sync(0xFFFFFFFFu, sq, 4);
                sq += __shfl_xor_sync(0xFFFFFFFFu, sq, 8);
                if ((p & 15) == 0) norms[mrow] += sq;   // same unique writer each chunk
                __nv_bfloat162 h0 = __float22bfloat162_rn(make_float2(v.x, v.y));
                __nv_bfloat162 h1 = __float22bfloat162_rn(make_float2(v.z, v.w));
                uint2 w;
                w.x = *reinterpret_cast<uint32_t*>(&h0);
                w.y = *reinterpret_cast<uint32_t*>(&h1);
                uint32_t off = (uint32_t)(mrow * 128 + mseg * 8);
                *reinterpret_cast<uint2*>(smem + SM_M + slot * 16384 + SW128(off)) = w;
            }

            CP_ASYNC_WAIT_ALL();   // this thread's Q segs are in smem
            MBAR_ARRIVE((slot == 0) ? FULL0 : FULL1);   // release: covers STS + asyncs
        }
        __syncthreads();                  // consumers done; norms complete
        if (tid - 256 < NTILE)
            norms[tid - 256] = rsqrtf(fmaxf(norms[tid - 256], 1e-30f));
        __syncthreads();
    } else {
        // ================= CONSUMER (256 threads, 8 warps: 64q x 64n) =========
        const int wq = wid >> 1;          // 0..3
        const int wn = wid & 1;           // 0..1
        float acc[4][8][4];
#pragma unroll
        for (int mt = 0; mt < 4; mt++)
#pragma unroll
            for (int nt = 0; nt < 8; nt++)
#pragma unroll
                for (int v = 0; v < 4; v++) acc[mt][nt][v] = 0.0f;

        const int lrow = l & 15;
        const int lhi  = (l >> 4) * 16;
        int pf0 = 0, pf1 = 0;

        for (int c = 0; c < NCHUNK; c++) {
            const int slot = c & 1;
            if (slot == 0) { mbar_wait(FULL0, pf0); pf0 ^= 1; }
            else           { mbar_wait(FULL1, pf1); pf1 ^= 1; }
            const uint32_t qbase = sb + SM_Q + slot * 32768;
            const uint32_t mbase = sb + SM_M + slot * 16384;

#pragma unroll
            for (int ks = 0; ks < 4; ks++) {
                uint32_t b[4][4];
#pragma unroll
                for (int p4 = 0; p4 < 4; p4++) {
                    uint32_t off = (uint32_t)((wn * 64 + p4 * 16 + lrow) * 128 + ks * 32 + lhi);
                    LDSM_X4_T(b[p4][0], b[p4][1], b[p4][2], b[p4][3], mbase + SW128(off));
                }
#pragma unroll
                for (int mh = 0; mh < 2; mh++) {
                    uint32_t a[2][4];
#pragma unroll
                    for (int m2 = 0; m2 < 2; m2++) {
                        uint32_t off = (uint32_t)((wq * 64 + (mh * 2 + m2) * 16 + lrow) * 128 + ks * 32 + lhi);
                        LDSM_X4(a[m2][0], a[m2][1], a[m2][2], a[m2][3], qbase + SW128(off));
                    }
#pragma unroll
                    for (int m2 = 0; m2 < 2; m2++)
#pragma unroll
                        for (int nt = 0; nt < 8; nt++)
                            MMA_BF16(acc[mh * 2 + m2][nt], a[m2],
                                     b[nt >> 1][nt & 1], b[nt >> 1][(nt & 1) + 2]);
                }
            }
            MBAR_ARRIVE((slot == 0) ? EMPTY0 : EMPTY1);
        }
        __syncthreads();                  // producers finish norms
        __syncthreads();                  // invn published
        const float* invn = norms;

        // ---- epilogue: per-q-row argmax over this CTA's 128 n
#pragma unroll
        for (int mt = 0; mt < 4; mt++) {
#pragma unroll
            for (int sub = 0; sub < 2; sub++) {
                unsigned long long best = 0ull;
#pragma unroll
                for (int nt = 0; nt < 8; nt++) {
#pragma unroll
                    for (int cc = 0; cc < 2; cc++) {
                        int nl = wn * 64 + nt * 8 + 2 * (l & 3) + cc;
                        int n = ntile + nl;
                        if (n < N_MEM) {
                            float s = acc[mt][nt][sub * 2 + cc] * invn[nl];
                            unsigned long long key =
                                ((unsigned long long)fkey(s) << 32) |
                                (unsigned long long)(unsigned int)(~(unsigned int)n);
                            if (key > best) best = key;
                        }
                    }
                }
                unsigned long long o;
                o = __shfl_xor_sync(0xFFFFFFFFu, best, 1); if (o > best) best = o;
                o = __shfl_xor_sync(0xFFFFFFFFu, best, 2); if (o > best) best = o;
                if ((l & 3) == 0) {
                    int q = wq * 64 + mt * 16 + (l >> 2) + sub * 8;
                    atomicMax(&g_best[q], best);
                }
            }
        }
    }
}

// Exact fp32 recompute of the winner's cosine sim + threshold.
__global__ __launch_bounds__(256) void finalize_kernel(const float* __restrict__ Q,
                                                       const float* __restrict__ M) {
    __shared__ float sdq[256], sdm[256], sdp[256];
    const int b = blockIdx.x;
    const int tid = threadIdx.x;

    unsigned long long pk = g_best[b];
    int idx = (int)(~(unsigned int)(pk & 0xFFFFFFFFull));

    const float* q = Q + (size_t)b * D_DIM;
    const float* m = M + (size_t)idx * D_DIM;
    float dq = 0.f, dm = 0.f, dp = 0.f;
    for (int k = tid * 4; k < D_DIM; k += 256 * 4) {
        float4 qa = *reinterpret_cast<const float4*>(&q[k]);
        float4 mb = *reinterpret_cast<const float4*>(&m[k]);
        dq += qa.x * qa.x + qa.y * qa.y + qa.z * qa.z + qa.w * qa.w;
        dm += mb.x * mb.x + mb.y * mb.y + mb.z * mb.z + mb.w * mb.w;
        dp += qa.x * mb.x + qa.y * mb.y + qa.z * mb.z + qa.w * mb.w;
    }
    sdq[tid] = dq; sdm[tid] = dm; sdp[tid] = dp;
    __syncthreads();
    for (int s = 128; s > 0; s >>= 1) {
        if (tid < s) {
            sdq[tid] += sdq[tid + s];
            sdm[tid] += sdm[tid + s];
            sdp[tid] += sdp[tid + s];
        }
        __syncthreads();
    }
    if (tid == 0) {
        float sim = sdp[0] / fmaxf(sqrtf(sdq[0]) * sqrtf(sdm[0]), 1e-8f);
        g_sel[b] = (sim > 0.6f) ? idx : -1;
    }
}

__global__ __launch_bounds__(128) void decode_kernel(const float* __restrict__ M,
                                                     const float* __restrict__ W,
                                                     const float* __restrict__ bias,
                                                     float* __restrict__ out) {
    const int b = blockIdx.y;
    const int j = blockIdx.x * 128 + threadIdx.x;
    const int sel = g_sel[b];
    float r = 0.0f;
    if (sel >= 0) {
        const float* e = M + (size_t)sel * D_DIM;
        const float* w = W + (size_t)j * D_DIM;
        float s = 0.0f;
        for (int k = 0; k < D_DIM; k += 4) {
            float4 ev = *reinterpret_cast<const float4*>(&e[k]);
            float4 wv = *reinterpret_cast<const float4*>(&w[k]);
            s += ev.x * wv.x + ev.y * wv.y + ev.z * wv.z + ev.w * wv.w;
        }
        r = s + bias[j];
    }
    out[(size_t)b * D_DIM + j] = r;
}

extern "C" void kernel_launch(void* const* d_in, const int* in_sizes, int n_in,
                              void* d_out, int out_size) {
    const float* Q    = (const float*)d_in[0];
    const float* M    = (const float*)d_in[1];
    const float* W    = (const float*)d_in[2];
    const float* bias = (const float*)d_in[3];
    float* out = (float*)d_out;

    cudaFuncSetAttribute(simmax_mma, cudaFuncAttributeMaxDynamicSharedMemorySize, SMEM_TOTAL);

    prep_kernel<<<B_Q * D_DIM / 4 / 256, 256>>>(Q);
    simmax_mma<<<NBLK, 384, SMEM_TOTAL>>>(M);
    finalize_kernel<<<B_Q, 256>>>(Q, M);
    decode_kernel<<<dim3(D_DIM / 128, B_Q), 128>>>(M, W, bias, out);
}